// round 15
// baseline (speedup 1.0000x reference)
#include <cuda_runtime.h>
#include <cuda_bf16.h>

// Problem constants
#define Bsz   4
#define NODES 51
#define MODAL 4
#define SEQ   256
#define DM    128
#define DK    64
#define NBN   (Bsz * NODES)          // 204
#define GRID_N 32                    // table nodes per (bn, j)

__device__ __forceinline__ float fast_exp2(float x) {
    float y;
    asm("ex2.approx.ftz.f32 %0, %1;" : "=f"(y) : "f"(x));
    return y;
}

// ---- packed f32x2 helpers ----
typedef unsigned long long u64;
__device__ __forceinline__ u64 pk2(float lo, float hi) {
    u64 r;
    asm("mov.b64 %0, {%1, %2};" : "=l"(r) : "f"(lo), "f"(hi));
    return r;
}
__device__ __forceinline__ void upk2(u64 p, float& lo, float& hi) {
    asm("mov.b64 {%0, %1}, %2;" : "=f"(lo), "=f"(hi) : "l"(p));
}
__device__ __forceinline__ u64 mul2(u64 a, u64 b) {
    u64 r;
    asm("mul.rn.f32x2 %0, %1, %2;" : "=l"(r) : "l"(a), "l"(b));
    return r;
}
__device__ __forceinline__ u64 fma2(u64 a, u64 b, u64 c) {
    u64 r;
    asm("fma.rn.f32x2 %0, %1, %2, %3;" : "=l"(r) : "l"(a), "l"(b), "l"(c));
    return r;
}
__device__ __forceinline__ u64 add2(u64 a, u64 b) {
    u64 r;
    asm("add.rn.f32x2 %0, %1, %2;" : "=l"(r) : "l"(a), "l"(b));
    return r;
}

// ---------------------------------------------------------------------------
// ONE kernel (single launch — R8's shell, measured 0.5us harness overhead).
// Block = bn (204 x 512 threads, 16 warps).
// Phase 1 (overlapped loads): warps 0-7 load the x tile + per-warp min/max;
//         ALL warps issue their weight loads (96 KB/block, L2-broadcast) —
//         the two load streams overlap in the memory system.
// Phase 2: finalize {A2, C2, Wm, Bm} (warp 0) -> smem; one barrier.
// Phase 3: tabulate f_j on a 32-node grid. Warp-uniform (j, seg):
//          j = wid>>2, seg = wid&3, g = lane. Pure LDS broadcast, 64 exps
//          per thread; seg partials combined via conflict-free smem.
// Phase 4: Catmull-Rom interpolation, 2 outputs per thread, all from smem.
// ---------------------------------------------------------------------------
__global__ __launch_bounds__(512, 2) void mmf_fused_kernel(
    const float* __restrict__ x,
    const float* __restrict__ Wq, const float* __restrict__ bq,
    const float* __restrict__ Wk,
    const float* __restrict__ Wv, const float* __restrict__ bv,
    float* __restrict__ out) {
    const int bn = blockIdx.x;
    const int tid = threadIdx.x;
    const int wid = tid >> 5;          // 0..15
    const int lane = tid & 31;

    __shared__ float4 sx4[MODAL][SEQ / 4];     // 4 KB x tile
    __shared__ float sF[MODAL][GRID_N];        // 512 B table
    __shared__ float sNum[3][MODAL][GRID_N];   // seg 1..3 partials (1.5 KB)
    __shared__ float sDen[3][MODAL][GRID_N];
    __shared__ float wpart[16][3];             // per-warp {pa, pc, pv}
    __shared__ float wmax[8], wmin[8];
    __shared__ float spb;                      // bv sum
    __shared__ float sc[4];                    // {A2, C2, Wm, Bm}

    // ---- Phase 1a: x tile + min/max (warps 0-7) ----
    if (tid < 256) {
        float4 v = ((const float4*)(x + (size_t)bn * (MODAL * SEQ)))[tid];
        ((float4*)sx4)[tid] = v;
        float mx = fmaxf(fmaxf(v.x, v.y), fmaxf(v.z, v.w));
        float mn = fminf(fminf(v.x, v.y), fminf(v.z, v.w));
#pragma unroll
        for (int off = 16; off; off >>= 1) {
            mx = fmaxf(mx, __shfl_xor_sync(0xffffffff, mx, off));
            mn = fminf(mn, __shfl_xor_sync(0xffffffff, mn, off));
        }
        if (lane == 0) { wmax[wid] = mx; wmin[wid] = mn; }
    }

    // ---- Phase 1b: weight prologue (ALL warps; overlaps with 1a's loads) ----
    {
        float pa = 0.f, pc = 0.f, pv = 0.f;
#pragma unroll
        for (int r = 0; r < 4; r++) {
            const int row = wid * 4 + r;
            float4 q  = ((const float4*)(Wq + row * DM))[lane];
            float4 kk = ((const float4*)(Wk + row * DM))[lane];
            float4 vv = ((const float4*)(Wv + row * DM))[lane];
            float sq = (q.x + q.y) + (q.z + q.w);
            float sk = (kk.x + kk.y) + (kk.z + kk.w);
            float sv = (vv.x + vv.y) + (vv.z + vv.w);
#pragma unroll
            for (int off = 16; off; off >>= 1) {
                sq += __shfl_xor_sync(0xffffffff, sq, off);
                sk += __shfl_xor_sync(0xffffffff, sk, off);
                sv += __shfl_xor_sync(0xffffffff, sv, off);
            }
            pa = fmaf(sq, sk, pa);
            pc = fmaf(bq[row], sk, pc);   // uniform broadcast load
            pv += sv;
        }
        if (lane == 0) {
            wpart[wid][0] = pa;
            wpart[wid][1] = pc;
            wpart[wid][2] = pv;
        }
        if (wid == 15) {
            float pb = bv[lane] + bv[lane + 32];
#pragma unroll
            for (int off = 16; off; off >>= 1) pb += __shfl_xor_sync(0xffffffff, pb, off);
            if (lane == 0) spb = pb;
        }
    }
    __syncthreads();

    // ---- Phase 2: finalize scalars (warp 0) ----
    if (wid == 0) {
        float qa = (lane < 16) ? wpart[lane][0] : 0.f;
        float qc = (lane < 16) ? wpart[lane][1] : 0.f;
        float qv = (lane < 16) ? wpart[lane][2] : 0.f;
#pragma unroll
        for (int off = 8; off; off >>= 1) {
            qa += __shfl_xor_sync(0xffffffff, qa, off);
            qc += __shfl_xor_sync(0xffffffff, qc, off);
            qv += __shfl_xor_sync(0xffffffff, qv, off);
        }
        if (lane == 0) {
            const float K = 0.125f * 1.4426950408889634f;  // log2e/sqrt(64)
            sc[0] = qa * K;                                 // A2
            sc[1] = qc * K;                                 // C2
            sc[2] = qv * (1.0f / DK) * (1.0f / (MODAL - 1));  // Wm
            sc[3] = spb * (1.0f / DK);                      // Bm
        }
    }
    __syncthreads();

    // Every thread derives scalars + grid params in registers (no extra sync)
    const float A2  = sc[0];
    const float C2s = sc[1];
    const float Wm  = sc[2];
    const float Bm  = sc[3];
    float tmx = wmax[0], tmn = wmin[0];
#pragma unroll
    for (int k = 1; k < 8; k++) {
        tmx = fmaxf(tmx, wmax[k]);
        tmn = fminf(tmn, wmin[k]);
    }
    const float a_c1 = fmaf(A2, tmn, C2s);
    const float a_c2 = fmaf(A2, tmx, C2s);
    const float alo = fminf(a_c1, a_c2);
    const float ahi = fmaxf(a_c1, a_c2);
    const float h = (ahi - alo) * (1.0f / (GRID_N - 1));
    const float invh = (ahi > alo) ? (float)(GRID_N - 1) / (ahi - alo) : 0.0f;

    // ---- Phase 3: tabulate. Warp-uniform (j, seg); g = lane ----
    {
        const int j   = wid >> 2;      // warp-uniform
        const int seg = wid & 3;       // warp-uniform t-quarter
        const int g   = lane;          // 0..31

        const float ag = fmaf(h, (float)g, alo);
        const u64 a22 = pk2(ag, ag);

        u64 num01 = 0ull, num23 = 0ull;
        u64 den01 = 0ull, den23 = 0ull;
        // all 32 lanes read the SAME address each iteration -> LDS broadcast
        const ulonglong2* __restrict__ row =
            ((const ulonglong2*)&sx4[j][0]) + seg * (SEQ / 16);
#pragma unroll 8
        for (int t4 = 0; t4 < SEQ / 16; t4++) {     // 16 iters x 4 elements
            ulonglong2 xt = row[t4];
            u64 p01 = mul2(a22, xt.x);
            u64 p23 = mul2(a22, xt.y);
            float p0, p1, p2, p3;
            upk2(p01, p0, p1);
            upk2(p23, p2, p3);
            float e0 = fast_exp2(p0);
            float e1 = fast_exp2(p1);
            float e2 = fast_exp2(p2);
            float e3 = fast_exp2(p3);
            u64 e01 = pk2(e0, e1);
            u64 e23 = pk2(e2, e3);
            num01 = fma2(xt.x, e01, num01);
            num23 = fma2(xt.y, e23, num23);
            den01 = add2(den01, e01);
            den23 = add2(den23, e23);
        }
        float n0, n1, n2, n3, d0, d1, d2, d3;
        upk2(num01, n0, n1);
        upk2(num23, n2, n3);
        upk2(den01, d0, d1);
        upk2(den23, d2, d3);
        float num = (n0 + n1) + (n2 + n3);
        float den = (d0 + d1) + (d2 + d3);

        if (seg != 0) {
            sNum[seg - 1][j][g] = num;
            sDen[seg - 1][j][g] = den;
        }
        __syncthreads();
        if (seg == 0) {
            num += (sNum[0][j][g] + sNum[1][j][g]) + sNum[2][j][g];
            den += (sDen[0][j][g] + sDen[1][j][g]) + sDen[2][j][g];
            sF[j][g] = __fdividef(num, den);
        }
    }
    __syncthreads();

    // ---- Phase 4: interpolate. 2 outputs per thread ----
#pragma unroll
    for (int rep = 0; rep < 2; rep++) {
        const int idx = tid + rep * 512;     // (i, s) = (idx>>8, idx&255)
        const int i = idx >> 8;

        const float xi = ((const float*)sx4)[idx];
        const float a2 = fmaf(A2, xi, C2s);

        float u = (a2 - alo) * invh;
        int i1 = (int)floorf(u);
        i1 = max(0, min(GRID_N - 2, i1));
        float fr = fminf(fmaxf(u - (float)i1, 0.0f), 1.0f);
        const int im  = max(i1 - 1, 0);
        const int ip2 = min(i1 + 2, GRID_N - 1);

        float acc = 0.f;
#pragma unroll
        for (int j = 0; j < MODAL; j++) {
            if (j == i) continue;
            float p0 = sF[j][im];
            float p1 = sF[j][i1];
            float p2 = sF[j][i1 + 1];
            float p3 = sF[j][ip2];
            // Catmull-Rom
            float c3 = 3.0f * (p1 - p2) + (p3 - p0);
            float c2 = 2.0f * p0 - 5.0f * p1 + 4.0f * p2 - p3;
            float c1 = p2 - p0;
            float f = fmaf(0.5f * fr, fmaf(fr, fmaf(fr, c3, c2), c1), p1);
            acc += f;
        }

        out[(size_t)bn * (MODAL * SEQ) + idx] = fmaf(Wm, acc, Bm);
    }
}

// ---------------------------------------------------------------------------
// Launch: ONE kernel.
// ---------------------------------------------------------------------------
extern "C" void kernel_launch(void* const* d_in, const int* in_sizes, int n_in,
                              void* d_out, int out_size) {
    const float* x  = (const float*)d_in[0];
    const float* Wq = (const float*)d_in[1];
    const float* bq = (const float*)d_in[2];
    const float* Wk = (const float*)d_in[3];
    const float* Wv = (const float*)d_in[5];
    const float* bv = (const float*)d_in[6];
    float* out = (float*)d_out;

    mmf_fused_kernel<<<NBN, 512>>>(x, Wq, bq, Wk, Wv, bv, out);
}